// round 6
// baseline (speedup 1.0000x reference)
#include <cuda_runtime.h>
#include <math.h>

#define NB   32      // batch
#define NC   512     // channels
#define HW   4096    // 64*64
#define NSEG 129     // segment ids 0..128 (0 dropped later)
#define NSG  128     // kept segments
#define NCLS 19
#define ATTH 512
#define MTOT (NB * NSG)   // 4096 GEMM rows

typedef unsigned long long u64;

#define FMA_F32X2(d, a, b, c) \
    asm("fma.rn.f32x2 %0, %1, %2, %3;" : "=l"(d) : "l"(a), "l"(b), "l"(c))
#define PACK_DUP_F32X2(d, s) \
    asm("mov.b64 %0, {%1, %1};" : "=l"(d) : "r"(__float_as_uint(s)))
#define UNPACK_F32X2(lo, hi, in) \
    asm("mov.b64 {%0, %1}, %2;" : "=r"(lo), "=r"(hi) : "l"(in))

// ---- scratch (device globals; no allocation allowed) ----
__device__ int   g_ids[NB * HW];
__device__ int   g_cnt[NB * NSEG];
__device__ float g_invc[NB * NSEG];
__device__ float g_means[NB * NSG * NC];    // [m][c] for wm_kernel
__device__ float g_meansT[NC * MTOT];       // [c][m] for the GEMM (A, m-contig)
__device__ float g_att[MTOT];

// ============================================================
// Kernel 0: zero counters / att accumulator, init out = bh.
// ============================================================
__global__ void zero_kernel(const float* __restrict__ bh,
                            float* __restrict__ out) {
    int t = blockIdx.x * 256 + threadIdx.x;   // grid 17 -> 4352
    if (t < MTOT) g_att[t] = 0.0f;
    if (t < NB * NSEG) g_cnt[t] = 0;
    if (t < NB * NCLS) out[t] = bh[t % NCLS];
}

// ============================================================
// Kernel 1: downsample mask -> ids, per-block hist -> global cnt.
// Grid (8, NB), 256 threads: each block owns 512 pixels.
// ============================================================
__global__ void prep_kernel(const int* __restrict__ mask) {
    int b = blockIdx.y;
    int pbase = blockIdx.x * 512;
    __shared__ int cnt[NSEG];
    for (int t = threadIdx.x; t < NSEG; t += 256) cnt[t] = 0;
    __syncthreads();
    const int* mb = mask + (long long)b * 512 * 512;
    #pragma unroll
    for (int q = 0; q < 2; ++q) {
        int p = pbase + q * 256 + threadIdx.x;
        int i = p >> 6, j = p & 63;
        int id = mb[(i * 8) * 512 + j * 8];
        id = min(max(id, 0), NSEG - 1);   // safety clamp
        g_ids[b * HW + p] = id;
        atomicAdd(&cnt[id], 1);
    }
    __syncthreads();
    for (int t = threadIdx.x; t < NSEG; t += 256)
        if (cnt[t]) atomicAdd(&g_cnt[b * NSEG + t], cnt[t]);
}

// ============================================================
// Kernel 2 (tiny): counts -> inverse counts.
// ============================================================
__global__ void invc_kernel() {
    int t = threadIdx.x;   // 160 threads, grid NB
    int b = blockIdx.x;
    if (t < NSEG) {
        int cv = g_cnt[b * NSEG + t];
        g_invc[b * NSEG + t] = (t >= 1 && cv > 0) ? (1.0f / (float)cv) : 0.0f;
    }
}

// ============================================================
// Kernel 3: segment sums, race-free via PER-WARP accumulator
// replication (no atomics, no ballot walk, fixed unrolled loop).
// Block = (32-channel chunk, batch), 128 threads / 4 warps.
// Warp w owns pixels [w*32, w*32+32) of each 128-px tile and a
// private acc copy s_acc[w][129][33] (lane = channel, stride 33
// -> conflict-free). Final: reduce 4 copies, write both layouts.
// ============================================================
#define SEG_SMEM ((32 * 129 + 4 * NSEG * 33) * 4)

__global__ void __launch_bounds__(128, 2)
seg_kernel(const float* __restrict__ x) {
    extern __shared__ float sseg[];
    float* s_tile = sseg;                 // [32 ch][129] pixel-in-tile
    float* s_acc  = sseg + 32 * 129;      // 4 copies of [129][33]
    __shared__ float s_invc[NSEG];

    int b = blockIdx.y;
    int cbase = blockIdx.x * 32;
    int tid = threadIdx.x;
    int w = tid >> 5, lane = tid & 31;

    for (int t = tid; t < 4 * NSEG * 33; t += 128) s_acc[t] = 0.0f;
    if (tid < NSEG) s_invc[tid] = g_invc[b * NSEG + tid];
    if (tid == 128 - 1) s_invc[NSEG - 1] = g_invc[b * NSEG + NSEG - 1];

    const float4* x4 = (const float4*)x;
    long long xbase = (long long)(b * NC + cbase) * (HW / 4);
    int cf = tid >> 2, qf = tid & 3;      // fill: channel cf, f4-slot qf(+4k)
    const int* idsb = g_ids + b * HW;
    float* acc = s_acc + w * (NSEG * 33);

    for (int tile = 0; tile < 32; ++tile) {
        __syncthreads();   // prior RMW done (and acc-zero on first iter)
        // stage 32ch x 128px (32 float4 per channel row), coalesced
        #pragma unroll
        for (int k = 0; k < 8; ++k) {
            int f4 = qf + 4 * k;
            float4 v = x4[xbase + (long long)cf * (HW / 4) + tile * 32 + f4];
            int o = cf * 129 + f4 * 4;
            s_tile[o + 0] = v.x; s_tile[o + 1] = v.y;
            s_tile[o + 2] = v.z; s_tile[o + 3] = v.w;
        }
        __syncthreads();
        // scatter: warp w owns pixels w*32..w*32+31 (no races)
        int idv = idsb[tile * 128 + w * 32 + lane];
        const float* tv = s_tile + lane * 129 + w * 32;
        #pragma unroll
        for (int j = 0; j < 32; ++j) {
            int id = __shfl_sync(0xffffffffu, idv, j);
            acc[id * 33 + lane] += tv[j];
        }
    }
    __syncthreads();

    // reduce 4 copies + write means [m][c] (coalesced over c)
    for (int t = tid; t < NSG * 32; t += 128) {
        int c = t & 31, sm1 = t >> 5;
        int o = (sm1 + 1) * 33 + c;
        float v = s_acc[o] + s_acc[NSEG * 33 + o] +
                  s_acc[2 * NSEG * 33 + o] + s_acc[3 * NSEG * 33 + o];
        g_means[((long long)b * NSG + sm1) * NC + cbase + c] = v * s_invc[sm1 + 1];
    }
    // write meansT [c][m] (coalesced over segment)
    for (int t = tid; t < NSG * 32; t += 128) {
        int sm1 = t & 127, c = t >> 7;
        int o = (sm1 + 1) * 33 + c;
        float v = s_acc[o] + s_acc[NSEG * 33 + o] +
                  s_acc[2 * NSEG * 33 + o] + s_acc[3 * NSEG * 33 + o];
        g_meansT[(long long)(cbase + c) * MTOT + b * NSG + sm1] = v * s_invc[sm1 + 1];
    }
}

// ============================================================
// Kernel 4: att logits GEMM. hidden = relu(meansT' @ Wa1 + ba1);
// g_att[m] += hidden_tile @ Wa2 (hidden never stored).
// BM=128, BN=64, BK=32, double-buffered, 256 thr, 8m x 4n f32x2.
// ============================================================
#define GBM 128
#define GBN 64
#define GBK 32
#define ASTR 136                 // row stride (words), 16B-aligned rows
#define GEMM_SMEM ((2 * GBK * ASTR + 2 * GBK * GBN) * 4)

__global__ void __launch_bounds__(256, 2)
att_gemm_kernel(const float* __restrict__ Wa1,
                const float* __restrict__ ba1,
                const float* __restrict__ Wa2) {
    extern __shared__ float sm[];
    float* AstBuf = sm;                       // 2 * 32*136
    float* BsBuf  = sm + 2 * GBK * ASTR;      // 2 * 32*64

    int tid = threadIdx.x;
    int mbase = blockIdx.y * GBM;
    int nbase = blockIdx.x * GBN;
    int tx = tid & 15, ty = tid >> 4;         // n = tx*4, m = ty*8

    // fill mappings (all coalesced, all vector ops)
    int am = tid & 31, akr = tid >> 5;        // A: m-chunk am*4, k-row akr(+8p)
    int br = tid >> 4, bc = (tid & 15) * 4;   // B: k-row br(+16p), n bc..bc+3
    const float* Ag = g_meansT + (long long)akr * MTOT + mbase + am * 4;
    const float* Bg = Wa1 + (long long)br * ATTH + nbase + bc;

    u64 acc2[4][4];
    #pragma unroll
    for (int i = 0; i < 4; ++i)
        #pragma unroll
        for (int j = 0; j < 4; ++j) acc2[i][j] = 0ULL;

    float4 pa[4], pb[2];
    #pragma unroll
    for (int p = 0; p < 4; ++p) pa[p] = *(const float4*)(Ag + (long long)(8 * p) * MTOT);
    #pragma unroll
    for (int p = 0; p < 2; ++p) pb[p] = *(const float4*)(Bg + (long long)(16 * p) * ATTH);

    const int NITER = NC / GBK;   // 16
    int cur = 0;
    #pragma unroll 1
    for (int it = 0; it < NITER; ++it) {
        float* Ac = AstBuf + cur * GBK * ASTR;
        float* Bc = BsBuf + cur * GBK * GBN;
        #pragma unroll
        for (int p = 0; p < 4; ++p)
            *(float4*)(Ac + (akr + 8 * p) * ASTR + am * 4) = pa[p];
        #pragma unroll
        for (int p = 0; p < 2; ++p)
            *(float4*)(Bc + (br + 16 * p) * GBN + bc) = pb[p];
        __syncthreads();

        if (it + 1 < NITER) {
            long long k0n = (long long)(it + 1) * GBK;
            #pragma unroll
            for (int p = 0; p < 4; ++p)
                pa[p] = *(const float4*)(Ag + (k0n + 8 * p) * MTOT);
            #pragma unroll
            for (int p = 0; p < 2; ++p)
                pb[p] = *(const float4*)(Bg + (k0n + 16 * p) * ATTH);
        }

        #pragma unroll
        for (int kk = 0; kk < GBK; ++kk) {
            const float* Ak = Ac + kk * ASTR + ty * 8;
            ulonglong2 a01 = *(const ulonglong2*)(Ak);       // m pairs 0,1
            ulonglong2 a23 = *(const ulonglong2*)(Ak + 4);   // m pairs 2,3
            float4 b4 = *(const float4*)(Bc + kk * GBN + tx * 4);
            u64 a2[4] = { a01.x, a01.y, a23.x, a23.y };
            u64 bd[4];
            PACK_DUP_F32X2(bd[0], b4.x);
            PACK_DUP_F32X2(bd[1], b4.y);
            PACK_DUP_F32X2(bd[2], b4.z);
            PACK_DUP_F32X2(bd[3], b4.w);
            #pragma unroll
            for (int mp = 0; mp < 4; ++mp) {
                FMA_F32X2(acc2[mp][0], a2[mp], bd[0], acc2[mp][0]);
                FMA_F32X2(acc2[mp][1], a2[mp], bd[1], acc2[mp][1]);
                FMA_F32X2(acc2[mp][2], a2[mp], bd[2], acc2[mp][2]);
                FMA_F32X2(acc2[mp][3], a2[mp], bd[3], acc2[mp][3]);
            }
        }
        cur ^= 1;
    }

    // epilogue: relu(acc + ba1) dot Wa2, reduce across the 16 tx lanes
    float b1[4], w2[4];
    #pragma unroll
    for (int j = 0; j < 4; ++j) {
        int n = nbase + tx * 4 + j;
        b1[j] = ba1[n];
        w2[j] = Wa2[n];
    }
    #pragma unroll
    for (int mp = 0; mp < 4; ++mp) {
        float p0 = 0.0f, p1 = 0.0f;
        #pragma unroll
        for (int j = 0; j < 4; ++j) {
            unsigned lo, hi;
            UNPACK_F32X2(lo, hi, acc2[mp][j]);
            float h0 = fmaxf(__uint_as_float(lo) + b1[j], 0.0f);
            float h1 = fmaxf(__uint_as_float(hi) + b1[j], 0.0f);
            p0 += h0 * w2[j];
            p1 += h1 * w2[j];
        }
        #pragma unroll
        for (int o = 8; o > 0; o >>= 1) {
            p0 += __shfl_xor_sync(0xffffffffu, p0, o);
            p1 += __shfl_xor_sync(0xffffffffu, p1, o);
        }
        if (tx == 0) {
            atomicAdd(&g_att[mbase + ty * 8 + 2 * mp + 0], p0);
            atomicAdd(&g_att[mbase + ty * 8 + 2 * mp + 1], p1);
        }
    }
}

// ============================================================
// Kernel 5: fused softmax + weighted mean + partial class dots.
// Grid (4 channel-groups, 32 batches), 128 threads.
// ============================================================
__global__ void wm_kernel(const float* __restrict__ Wh,
                          const float* __restrict__ ba2,
                          float* __restrict__ out) {
    int b = blockIdx.y, cg = blockIdx.x, t = threadIdx.x;
    int lane = t & 31, w = t >> 5;
    __shared__ float satt[NSG];
    __shared__ float red[4];

    float v = g_att[b * NSG + t] + ba2[0];
    float m = v;
    #pragma unroll
    for (int o = 16; o > 0; o >>= 1) m = fmaxf(m, __shfl_xor_sync(0xffffffffu, m, o));
    if (lane == 0) red[w] = m;
    __syncthreads();
    m = fmaxf(fmaxf(red[0], red[1]), fmaxf(red[2], red[3]));
    float e = expf(v - m);
    float s = e;
    #pragma unroll
    for (int o = 16; o > 0; o >>= 1) s += __shfl_xor_sync(0xffffffffu, s, o);
    __syncthreads();
    if (lane == 0) red[w] = s;
    __syncthreads();
    s = red[0] + red[1] + red[2] + red[3];
    satt[t] = e / s;
    __syncthreads();

    int c = cg * 128 + t;
    float wm = 0.0f;
    const float* mp = g_means + (long long)b * NSG * NC + c;
    #pragma unroll 8
    for (int sg = 0; sg < NSG; ++sg) wm += satt[sg] * mp[(long long)sg * NC];

    const float* whr = Wh + (long long)c * NCLS;
    #pragma unroll 1
    for (int cls = 0; cls < NCLS; ++cls) {
        float p = wm * whr[cls];
        #pragma unroll
        for (int o = 16; o > 0; o >>= 1) p += __shfl_xor_sync(0xffffffffu, p, o);
        if (lane == 0) atomicAdd(&out[b * NCLS + cls], p);
    }
}

// ============================================================
// Kernel 6: BCE-with-logits loss, mean over all 608 elements.
// ============================================================
__global__ void loss_kernel(const float* __restrict__ target,
                            float* __restrict__ out, int out_size) {
    const int n = NB * NCLS;   // 608
    int t = threadIdx.x;
    float v = 0.0f;
    if (t < n) {
        float l = out[t];
        float tg = target[t];
        v = fmaxf(l, 0.0f) - l * tg + log1pf(expf(-fabsf(l)));
    }
    __shared__ float red[32];
    int lane = t & 31, warp = t >> 5;
    #pragma unroll
    for (int o = 16; o > 0; o >>= 1) v += __shfl_xor_sync(0xffffffffu, v, o);
    if (lane == 0) red[warp] = v;
    __syncthreads();
    if (t < 32) {
        float s = (t < 20) ? red[t] : 0.0f;
        #pragma unroll
        for (int o = 16; o > 0; o >>= 1) s += __shfl_xor_sync(0xffffffffu, s, o);
        if (t == 0) out[out_size - 1] = s / (float)n;
    }
}

// ============================================================
extern "C" void kernel_launch(void* const* d_in, const int* in_sizes, int n_in,
                              void* d_out, int out_size) {
    const float* x      = (const float*)d_in[0];
    const int*   mask   = (const int*)d_in[1];
    const float* target = (const float*)d_in[2];
    const float* Wa1    = (const float*)d_in[3];
    const float* ba1    = (const float*)d_in[4];
    const float* Wa2    = (const float*)d_in[5];
    const float* ba2    = (const float*)d_in[6];
    const float* Wh     = (const float*)d_in[7];
    const float* bh     = (const float*)d_in[8];
    float* out = (float*)d_out;

    cudaFuncSetAttribute(seg_kernel,
                         cudaFuncAttributeMaxDynamicSharedMemorySize, SEG_SMEM);
    cudaFuncSetAttribute(att_gemm_kernel,
                         cudaFuncAttributeMaxDynamicSharedMemorySize, GEMM_SMEM);

    zero_kernel<<<17, 256>>>(bh, out);                                   // idx 0
    prep_kernel<<<dim3(8, NB), 256>>>(mask);                             // idx 1
    invc_kernel<<<NB, 160>>>();                                          // idx 2
    seg_kernel<<<dim3(16, NB), 128, SEG_SMEM>>>(x);                      // idx 3 (profiled)
    att_gemm_kernel<<<dim3(ATTH / GBN, MTOT / GBM), 256, GEMM_SMEM>>>(Wa1, ba1, Wa2); // idx 4
    wm_kernel<<<dim3(4, NB), 128>>>(Wh, ba2, out);                       // idx 5
    loss_kernel<<<1, 640>>>(target, out, out_size);                      // idx 6
}

// round 7
// speedup vs baseline: 1.2616x; 1.2616x over previous
#include <cuda_runtime.h>
#include <math.h>

#define NB   32      // batch
#define NC   512     // channels
#define HW   4096    // 64*64
#define NSEG 129     // segment ids 0..128 (0 dropped later)
#define NSG  128     // kept segments
#define NCLS 19
#define ATTH 512
#define MTOT (NB * NSG)   // 4096 GEMM rows
#define NTILE 32          // 128-pixel tiles per batch

typedef unsigned long long u64;

#define FMA_F32X2(d, a, b, c) \
    asm("fma.rn.f32x2 %0, %1, %2, %3;" : "=l"(d) : "l"(a), "l"(b), "l"(c))
#define PACK_DUP_F32X2(d, s) \
    asm("mov.b64 %0, {%1, %1};" : "=l"(d) : "r"(__float_as_uint(s)))
#define UNPACK_F32X2(lo, hi, in) \
    asm("mov.b64 {%0, %1}, %2;" : "=r"(lo), "=r"(hi) : "l"(in))

// ---- scratch (device globals; no allocation allowed) ----
__device__ int   g_cnt[NB * NSEG];
__device__ float g_invc[NB * NSEG];
__device__ int   g_sorted[NB * HW];          // per tile: 128 packed (id<<7|pos)
__device__ int   g_toff[NB * NTILE * 8];     // per tile: warp start offsets
__device__ float g_means[NB * NSG * NC];     // [m][c] for wm_kernel
__device__ float g_meansT[NC * MTOT];        // [c][m] for the GEMM
__device__ float g_att[MTOT];

// ============================================================
// Kernel 0: zero counters / att accumulator, init out = bh.
// ============================================================
__global__ void zero_kernel(const float* __restrict__ bh,
                            float* __restrict__ out) {
    int t = blockIdx.x * 256 + threadIdx.x;   // grid 17 -> 4352
    if (t < MTOT) g_att[t] = 0.0f;
    if (t < NB * NSEG) g_cnt[t] = 0;
    if (t < NB * NCLS) out[t] = bh[t % NCLS];
}

// ============================================================
// Kernel 1: downsample + per-tile counting sort of segment ids.
// Block = (tile, batch), 128 threads (one per pixel of the tile).
// Emits packed sorted entries (id<<7 | pos) and per-warp start
// offsets (warp w of seg_kernel owns ids [16w, 16w+16); warp 7
// also takes id 128). Also accumulates global per-(b,id) counts.
// ============================================================
__global__ void prep_sort_kernel(const int* __restrict__ mask) {
    int b = blockIdx.y, tile = blockIdx.x;
    int t = threadIdx.x;
    __shared__ int hist[NSEG];
    __shared__ int pref[NSEG];
    __shared__ int sid[128];

    for (int i = t; i < NSEG; i += 128) hist[i] = 0;
    __syncthreads();

    int p = tile * 128 + t;
    int i = p >> 6, j = p & 63;
    int id = mask[((long long)b * 512 + i * 8) * 512 + j * 8];
    id = min(max(id, 0), NSEG - 1);
    sid[t] = id;
    atomicAdd(&hist[id], 1);
    __syncthreads();

    if (t == 0) {
        int s = 0;
        for (int k = 0; k < NSEG; ++k) { pref[k] = s; s += hist[k]; }
    }
    __syncthreads();

    for (int k = t; k < NSEG; k += 128)
        if (hist[k]) atomicAdd(&g_cnt[b * NSEG + k], hist[k]);
    if (t < 8) g_toff[(b * NTILE + tile) * 8 + t] = pref[t * 16];
    __syncthreads();   // toff reads done before pref is mutated

    int rank = atomicAdd(&pref[sid[t]], 1);
    g_sorted[(b * NTILE + tile) * 128 + rank] = (sid[t] << 7) | t;
}

// ============================================================
// Kernel 2 (tiny): counts -> inverse counts.
// ============================================================
__global__ void invc_kernel() {
    int t = threadIdx.x;   // 160 threads, grid NB
    int b = blockIdx.x;
    if (t < NSEG) {
        int cv = g_cnt[b * NSEG + t];
        g_invc[b * NSEG + t] = (t >= 1 && cv > 0) ? (1.0f / (float)cv) : 0.0f;
    }
}

// ============================================================
// Kernel 3: segment sums. Warp w owns segment ids [16w,16w+16)
// (sorted entries make that a contiguous slice) -> ONE shared
// accumulator, no races, no atomics, no ballot. Runs of equal id
// collapse in a register before flushing.
// Block = (32-ch chunk, batch), 256 threads, smem ~34KB -> 6/SM.
// s_tile layout [pos][c] stride 33: staging stores, scatter
// reads, and acc RMWs all bank-conflict-free.
// ============================================================
#define SEG_SMEM ((128 * 33 + NSEG * 33) * 4)

__global__ void __launch_bounds__(256, 6)
seg_kernel(const float* __restrict__ x) {
    extern __shared__ float sseg[];
    float* s_tile = sseg;               // [128 pos][33] (col = channel)
    float* s_acc  = sseg + 128 * 33;    // [129 id][33]
    __shared__ int s_sorted[128];
    __shared__ int s_off[8];
    __shared__ float s_invc[NSEG];

    int b = blockIdx.y;
    int cbase = blockIdx.x * 32;
    int tid = threadIdx.x;
    int w = tid >> 5, lane = tid & 31;

    for (int t = tid; t < NSEG * 33; t += 256) s_acc[t] = 0.0f;
    for (int t = tid; t < NSEG; t += 256) s_invc[t] = g_invc[b * NSEG + t];

    int cf = tid >> 3, qf = tid & 7;    // staging: channel cf, f4-slot qf(+8k)
    const float4* xp = (const float4*)x + (long long)(b * NC + cbase + cf) * (HW / 4);
    const int* sortb = g_sorted + (long long)b * HW;
    const int* toffb = g_toff + b * NTILE * 8;

    for (int tile = 0; tile < NTILE; ++tile) {
        __syncthreads();   // prior scatter done (and acc-zero first iter)
        if (tid < 128) s_sorted[tid] = sortb[tile * 128 + tid];
        else if (tid < 136) s_off[tid - 128] = toffb[tile * 8 + (tid - 128)];
        // stage 128px x 32ch into [pos][c] (conflict-free scalar STS)
        #pragma unroll
        for (int k = 0; k < 4; ++k) {
            int f4 = qf + 8 * k;
            float4 v = xp[tile * 32 + f4];
            float* o = s_tile + (f4 * 4) * 33 + cf;
            o[0] = v.x; o[33] = v.y; o[66] = v.z; o[99] = v.w;
        }
        __syncthreads();

        int e   = s_off[w];
        int end = (w == 7) ? 128 : s_off[w + 1];
        if (e < end) {
            int s = s_sorted[e];
            int cid = s >> 7;
            float r = s_tile[(s & 127) * 33 + lane];
            for (++e; e < end; ++e) {
                s = s_sorted[e];
                int id = s >> 7;
                float v = s_tile[(s & 127) * 33 + lane];
                if (id != cid) {               // uniform branch
                    s_acc[cid * 33 + lane] += r;
                    cid = id; r = v;
                } else {
                    r += v;
                }
            }
            s_acc[cid * 33 + lane] += r;
        }
    }
    __syncthreads();

    // write means [m][c] (coalesced over c)
    for (int t = tid; t < NSG * 32; t += 256) {
        int c = t & 31, sm1 = t >> 5;
        g_means[((long long)b * NSG + sm1) * NC + cbase + c] =
            s_acc[(sm1 + 1) * 33 + c] * s_invc[sm1 + 1];
    }
    // write meansT [c][m] (coalesced over segment)
    for (int t = tid; t < NSG * 32; t += 256) {
        int sm1 = t & 127, c = t >> 7;
        g_meansT[(long long)(cbase + c) * MTOT + b * NSG + sm1] =
            s_acc[(sm1 + 1) * 33 + c] * s_invc[sm1 + 1];
    }
}

// ============================================================
// Kernel 4: att logits GEMM. hidden = relu(meansT' @ Wa1 + ba1);
// g_att[m] += hidden_tile @ Wa2 (hidden never stored).
// BM=128, BN=64, BK=32, double-buffered, 256 thr, 8m x 4n f32x2.
// ============================================================
#define GBM 128
#define GBN 64
#define GBK 32
#define ASTR 136
#define GEMM_SMEM ((2 * GBK * ASTR + 2 * GBK * GBN) * 4)

__global__ void __launch_bounds__(256, 2)
att_gemm_kernel(const float* __restrict__ Wa1,
                const float* __restrict__ ba1,
                const float* __restrict__ Wa2) {
    extern __shared__ float sm[];
    float* AstBuf = sm;
    float* BsBuf  = sm + 2 * GBK * ASTR;

    int tid = threadIdx.x;
    int mbase = blockIdx.y * GBM;
    int nbase = blockIdx.x * GBN;
    int tx = tid & 15, ty = tid >> 4;

    int am = tid & 31, akr = tid >> 5;
    int br = tid >> 4, bc = (tid & 15) * 4;
    const float* Ag = g_meansT + (long long)akr * MTOT + mbase + am * 4;
    const float* Bg = Wa1 + (long long)br * ATTH + nbase + bc;

    u64 acc2[4][4];
    #pragma unroll
    for (int i = 0; i < 4; ++i)
        #pragma unroll
        for (int j = 0; j < 4; ++j) acc2[i][j] = 0ULL;

    float4 pa[4], pb[2];
    #pragma unroll
    for (int p = 0; p < 4; ++p) pa[p] = *(const float4*)(Ag + (long long)(8 * p) * MTOT);
    #pragma unroll
    for (int p = 0; p < 2; ++p) pb[p] = *(const float4*)(Bg + (long long)(16 * p) * ATTH);

    const int NITER = NC / GBK;
    int cur = 0;
    #pragma unroll 1
    for (int it = 0; it < NITER; ++it) {
        float* Ac = AstBuf + cur * GBK * ASTR;
        float* Bc = BsBuf + cur * GBK * GBN;
        #pragma unroll
        for (int p = 0; p < 4; ++p)
            *(float4*)(Ac + (akr + 8 * p) * ASTR + am * 4) = pa[p];
        #pragma unroll
        for (int p = 0; p < 2; ++p)
            *(float4*)(Bc + (br + 16 * p) * GBN + bc) = pb[p];
        __syncthreads();

        if (it + 1 < NITER) {
            long long k0n = (long long)(it + 1) * GBK;
            #pragma unroll
            for (int p = 0; p < 4; ++p)
                pa[p] = *(const float4*)(Ag + (k0n + 8 * p) * MTOT);
            #pragma unroll
            for (int p = 0; p < 2; ++p)
                pb[p] = *(const float4*)(Bg + (k0n + 16 * p) * ATTH);
        }

        #pragma unroll
        for (int kk = 0; kk < GBK; ++kk) {
            const float* Ak = Ac + kk * ASTR + ty * 8;
            ulonglong2 a01 = *(const ulonglong2*)(Ak);
            ulonglong2 a23 = *(const ulonglong2*)(Ak + 4);
            float4 b4 = *(const float4*)(Bc + kk * GBN + tx * 4);
            u64 a2[4] = { a01.x, a01.y, a23.x, a23.y };
            u64 bd[4];
            PACK_DUP_F32X2(bd[0], b4.x);
            PACK_DUP_F32X2(bd[1], b4.y);
            PACK_DUP_F32X2(bd[2], b4.z);
            PACK_DUP_F32X2(bd[3], b4.w);
            #pragma unroll
            for (int mp = 0; mp < 4; ++mp) {
                FMA_F32X2(acc2[mp][0], a2[mp], bd[0], acc2[mp][0]);
                FMA_F32X2(acc2[mp][1], a2[mp], bd[1], acc2[mp][1]);
                FMA_F32X2(acc2[mp][2], a2[mp], bd[2], acc2[mp][2]);
                FMA_F32X2(acc2[mp][3], a2[mp], bd[3], acc2[mp][3]);
            }
        }
        cur ^= 1;
    }

    float b1[4], w2[4];
    #pragma unroll
    for (int j = 0; j < 4; ++j) {
        int n = nbase + tx * 4 + j;
        b1[j] = ba1[n];
        w2[j] = Wa2[n];
    }
    #pragma unroll
    for (int mp = 0; mp < 4; ++mp) {
        float p0 = 0.0f, p1 = 0.0f;
        #pragma unroll
        for (int j = 0; j < 4; ++j) {
            unsigned lo, hi;
            UNPACK_F32X2(lo, hi, acc2[mp][j]);
            float h0 = fmaxf(__uint_as_float(lo) + b1[j], 0.0f);
            float h1 = fmaxf(__uint_as_float(hi) + b1[j], 0.0f);
            p0 += h0 * w2[j];
            p1 += h1 * w2[j];
        }
        #pragma unroll
        for (int o = 8; o > 0; o >>= 1) {
            p0 += __shfl_xor_sync(0xffffffffu, p0, o);
            p1 += __shfl_xor_sync(0xffffffffu, p1, o);
        }
        if (tx == 0) {
            atomicAdd(&g_att[mbase + ty * 8 + 2 * mp + 0], p0);
            atomicAdd(&g_att[mbase + ty * 8 + 2 * mp + 1], p1);
        }
    }
}

// ============================================================
// Kernel 5: fused softmax + weighted mean + partial class dots.
// ============================================================
__global__ void wm_kernel(const float* __restrict__ Wh,
                          const float* __restrict__ ba2,
                          float* __restrict__ out) {
    int b = blockIdx.y, cg = blockIdx.x, t = threadIdx.x;
    int lane = t & 31, w = t >> 5;
    __shared__ float satt[NSG];
    __shared__ float red[4];

    float v = g_att[b * NSG + t] + ba2[0];
    float m = v;
    #pragma unroll
    for (int o = 16; o > 0; o >>= 1) m = fmaxf(m, __shfl_xor_sync(0xffffffffu, m, o));
    if (lane == 0) red[w] = m;
    __syncthreads();
    m = fmaxf(fmaxf(red[0], red[1]), fmaxf(red[2], red[3]));
    float e = expf(v - m);
    float s = e;
    #pragma unroll
    for (int o = 16; o > 0; o >>= 1) s += __shfl_xor_sync(0xffffffffu, s, o);
    __syncthreads();
    if (lane == 0) red[w] = s;
    __syncthreads();
    s = red[0] + red[1] + red[2] + red[3];
    satt[t] = e / s;
    __syncthreads();

    int c = cg * 128 + t;
    float wm = 0.0f;
    const float* mp = g_means + (long long)b * NSG * NC + c;
    #pragma unroll 8
    for (int sg = 0; sg < NSG; ++sg) wm += satt[sg] * mp[(long long)sg * NC];

    const float* whr = Wh + (long long)c * NCLS;
    #pragma unroll 1
    for (int cls = 0; cls < NCLS; ++cls) {
        float p = wm * whr[cls];
        #pragma unroll
        for (int o = 16; o > 0; o >>= 1) p += __shfl_xor_sync(0xffffffffu, p, o);
        if (lane == 0) atomicAdd(&out[b * NCLS + cls], p);
    }
}

// ============================================================
// Kernel 6: BCE-with-logits loss, mean over all 608 elements.
// ============================================================
__global__ void loss_kernel(const float* __restrict__ target,
                            float* __restrict__ out, int out_size) {
    const int n = NB * NCLS;   // 608
    int t = threadIdx.x;
    float v = 0.0f;
    if (t < n) {
        float l = out[t];
        float tg = target[t];
        v = fmaxf(l, 0.0f) - l * tg + log1pf(expf(-fabsf(l)));
    }
    __shared__ float red[32];
    int lane = t & 31, warp = t >> 5;
    #pragma unroll
    for (int o = 16; o > 0; o >>= 1) v += __shfl_xor_sync(0xffffffffu, v, o);
    if (lane == 0) red[warp] = v;
    __syncthreads();
    if (t < 32) {
        float s = (t < 20) ? red[t] : 0.0f;
        #pragma unroll
        for (int o = 16; o > 0; o >>= 1) s += __shfl_xor_sync(0xffffffffu, s, o);
        if (t == 0) out[out_size - 1] = s / (float)n;
    }
}

// ============================================================
extern "C" void kernel_launch(void* const* d_in, const int* in_sizes, int n_in,
                              void* d_out, int out_size) {
    const float* x      = (const float*)d_in[0];
    const int*   mask   = (const int*)d_in[1];
    const float* target = (const float*)d_in[2];
    const float* Wa1    = (const float*)d_in[3];
    const float* ba1    = (const float*)d_in[4];
    const float* Wa2    = (const float*)d_in[5];
    const float* ba2    = (const float*)d_in[6];
    const float* Wh     = (const float*)d_in[7];
    const float* bh     = (const float*)d_in[8];
    float* out = (float*)d_out;

    cudaFuncSetAttribute(seg_kernel,
                         cudaFuncAttributeMaxDynamicSharedMemorySize, SEG_SMEM);
    cudaFuncSetAttribute(att_gemm_kernel,
                         cudaFuncAttributeMaxDynamicSharedMemorySize, GEMM_SMEM);

    zero_kernel<<<17, 256>>>(bh, out);                                   // idx 0
    prep_sort_kernel<<<dim3(NTILE, NB), 128>>>(mask);                    // idx 1
    invc_kernel<<<NB, 160>>>();                                          // idx 2
    seg_kernel<<<dim3(16, NB), 256, SEG_SMEM>>>(x);                      // idx 3 (profiled)
    att_gemm_kernel<<<dim3(ATTH / GBN, MTOT / GBM), 256, GEMM_SMEM>>>(Wa1, ba1, Wa2); // idx 4
    wm_kernel<<<dim3(4, NB), 128>>>(Wh, ba2, out);                       // idx 5
    loss_kernel<<<1, 640>>>(target, out, out_size);                      // idx 6
}

// round 8
// speedup vs baseline: 1.2996x; 1.0301x over previous
#include <cuda_runtime.h>
#include <math.h>

#define NB   32      // batch
#define NC   512     // channels
#define HW   4096    // 64*64
#define NSEG 129     // segment ids 0..128 (0 dropped later)
#define NSG  128     // kept segments
#define NCLS 19
#define ATTH 512
#define MTOT (NB * NSG)   // 4096 GEMM rows
#define NTILE 32          // 128-pixel tiles per batch

typedef unsigned long long u64;

#define FMA_F32X2(d, a, b, c) \
    asm("fma.rn.f32x2 %0, %1, %2, %3;" : "=l"(d) : "l"(a), "l"(b), "l"(c))
#define PACK_DUP_F32X2(d, s) \
    asm("mov.b64 %0, {%1, %1};" : "=l"(d) : "r"(__float_as_uint(s)))
#define UNPACK_F32X2(lo, hi, in) \
    asm("mov.b64 {%0, %1}, %2;" : "=r"(lo), "=r"(hi) : "l"(in))

// ---- scratch (device globals; no allocation allowed) ----
__device__ int   g_cnt[NB * NSEG];
__device__ float g_invc[NB * NSEG];
__device__ int   g_sorted[NB * HW];          // per tile: 128 packed ((id*33)<<16 | pos*33)
__device__ int   g_toff[NB * NTILE * 8];     // per tile: warp start offsets
__device__ float g_means[NB * NSG * NC];     // [m][c] for wm_kernel
__device__ float g_meansT[NC * MTOT];        // [c][m] for the GEMM
__device__ float g_att[MTOT];

// ============================================================
// Kernel 0: zero counters / att accumulator, init out = bh.
// ============================================================
__global__ void zero_kernel(const float* __restrict__ bh,
                            float* __restrict__ out) {
    int t = blockIdx.x * 256 + threadIdx.x;   // grid 17 -> 4352
    if (t < MTOT) g_att[t] = 0.0f;
    if (t < NB * NSEG) g_cnt[t] = 0;
    if (t < NB * NCLS) out[t] = bh[t % NCLS];
}

// ============================================================
// Kernel 1: downsample + per-tile counting sort of segment ids.
// Emits packed sorted entries ((id*33)<<16 | pos*33) -- both
// offsets premultiplied for the seg scatter -- plus per-warp
// start offsets (warp w owns ids [16w, 16w+16); warp 7 takes 128
// too). Also accumulates global per-(b,id) counts.
// ============================================================
__global__ void prep_sort_kernel(const int* __restrict__ mask) {
    int b = blockIdx.y, tile = blockIdx.x;
    int t = threadIdx.x;
    __shared__ int hist[NSEG];
    __shared__ int pref[NSEG];
    __shared__ int sid[128];

    for (int i = t; i < NSEG; i += 128) hist[i] = 0;
    __syncthreads();

    int p = tile * 128 + t;
    int i = p >> 6, j = p & 63;
    int id = mask[((long long)b * 512 + i * 8) * 512 + j * 8];
    id = min(max(id, 0), NSEG - 1);
    sid[t] = id;
    atomicAdd(&hist[id], 1);
    __syncthreads();

    if (t == 0) {
        int s = 0;
        for (int k = 0; k < NSEG; ++k) { pref[k] = s; s += hist[k]; }
    }
    __syncthreads();

    for (int k = t; k < NSEG; k += 128)
        if (hist[k]) atomicAdd(&g_cnt[b * NSEG + k], hist[k]);
    if (t < 8) g_toff[(b * NTILE + tile) * 8 + t] = pref[t * 16];
    __syncthreads();   // toff reads done before pref is mutated

    int rank = atomicAdd(&pref[sid[t]], 1);
    g_sorted[(b * NTILE + tile) * 128 + rank] = ((sid[t] * 33) << 16) | (t * 33);
}

// ============================================================
// Kernel 2 (tiny): counts -> inverse counts.
// ============================================================
__global__ void invc_kernel() {
    int t = threadIdx.x;   // 160 threads, grid NB
    int b = blockIdx.x;
    if (t < NSEG) {
        int cv = g_cnt[b * NSEG + t];
        g_invc[b * NSEG + t] = (t >= 1 && cv > 0) ? (1.0f / (float)cv) : 0.0f;
    }
}

// ============================================================
// Kernel 3: segment sums, sorted scatter + REGISTER PREFETCH.
// Warp w owns segment ids [16w,16w+16) (contiguous in sorted
// order) -> one shared accumulator, no races, no atomics.
// Tile t+1's x data + metadata are prefetched into registers
// right after tile t's staging sync, so DRAM latency overlaps
// the scatter phase instead of serializing with it.
// ============================================================
#define SEG_SMEM ((128 * 33 + NSEG * 33) * 4)

__global__ void __launch_bounds__(256, 6)
seg_kernel(const float* __restrict__ x) {
    extern __shared__ float sseg[];
    float* s_tile = sseg;               // [128 pos][33] (col = channel)
    float* s_acc  = sseg + 128 * 33;    // [129 id][33]
    __shared__ int s_sorted[128];
    __shared__ int s_off[8];
    __shared__ float s_invc[NSEG];

    int b = blockIdx.y;
    int cbase = blockIdx.x * 32;
    int tid = threadIdx.x;
    int w = tid >> 5, lane = tid & 31;

    for (int t = tid; t < NSEG * 33; t += 256) s_acc[t] = 0.0f;
    for (int t = tid; t < NSEG; t += 256) s_invc[t] = g_invc[b * NSEG + t];

    int cf = tid >> 3, qf = tid & 7;    // staging: channel cf, f4-slot qf(+8k)
    const float4* xp = (const float4*)x + (long long)(b * NC + cbase + cf) * (HW / 4);
    const int* sortb = g_sorted + (long long)b * HW;
    const int* toffb = g_toff + b * NTILE * 8;

    // prefetch tile 0
    float4 pf[4];
    int rsort = 0, roff = 0;
    #pragma unroll
    for (int k = 0; k < 4; ++k) pf[k] = xp[qf + 8 * k];
    if (tid < 128) rsort = sortb[tid];
    if (tid < 8)  roff  = toffb[tid];

    #pragma unroll 1
    for (int tile = 0; tile < NTILE; ++tile) {
        __syncthreads();   // scatter of tile-1 done (s_tile/s_sorted free); acc-zero on 1st
        // commit staged tile (conflict-free scalar STS)
        #pragma unroll
        for (int k = 0; k < 4; ++k) {
            int f4 = qf + 8 * k;
            float* o = s_tile + (f4 * 4) * 33 + cf;
            o[0] = pf[k].x; o[33] = pf[k].y; o[66] = pf[k].z; o[99] = pf[k].w;
        }
        if (tid < 128) s_sorted[tid] = rsort;
        if (tid < 8)   s_off[tid]    = roff;
        __syncthreads();   // staging visible

        // prefetch next tile (overlaps the scatter below)
        if (tile + 1 < NTILE) {
            #pragma unroll
            for (int k = 0; k < 4; ++k) pf[k] = xp[(tile + 1) * 32 + qf + 8 * k];
            if (tid < 128) rsort = sortb[(tile + 1) * 128 + tid];
            if (tid < 8)   roff  = toffb[(tile + 1) * 8 + tid];
        }

        // scatter current tile (premultiplied offsets: s>>16 = id*33, s&0xffff = pos*33)
        int e   = s_off[w];
        int end = (w == 7) ? 128 : s_off[w + 1];
        if (e < end) {
            int s = s_sorted[e];
            int cido = s >> 16;
            float r = s_tile[(s & 0xffff) + lane];
            for (++e; e < end; ++e) {
                s = s_sorted[e];
                int ido = s >> 16;
                float v = s_tile[(s & 0xffff) + lane];
                if (ido != cido) {             // uniform branch
                    s_acc[cido + lane] += r;
                    cido = ido; r = v;
                } else {
                    r += v;
                }
            }
            s_acc[cido + lane] += r;
        }
    }
    __syncthreads();

    // write means [m][c] (coalesced over c)
    for (int t = tid; t < NSG * 32; t += 256) {
        int c = t & 31, sm1 = t >> 5;
        g_means[((long long)b * NSG + sm1) * NC + cbase + c] =
            s_acc[(sm1 + 1) * 33 + c] * s_invc[sm1 + 1];
    }
    // write meansT [c][m] (coalesced over segment)
    for (int t = tid; t < NSG * 32; t += 256) {
        int sm1 = t & 127, c = t >> 7;
        g_meansT[(long long)(cbase + c) * MTOT + b * NSG + sm1] =
            s_acc[(sm1 + 1) * 33 + c] * s_invc[sm1 + 1];
    }
}

// ============================================================
// Kernel 4: att logits GEMM. hidden = relu(meansT' @ Wa1 + ba1);
// g_att[m] += hidden_tile @ Wa2 (hidden never stored).
// BM=128, BN=64, BK=32, double-buffered, 256 thr, 8m x 4n f32x2.
// ============================================================
#define GBM 128
#define GBN 64
#define GBK 32
#define ASTR 136
#define GEMM_SMEM ((2 * GBK * ASTR + 2 * GBK * GBN) * 4)

__global__ void __launch_bounds__(256, 2)
att_gemm_kernel(const float* __restrict__ Wa1,
                const float* __restrict__ ba1,
                const float* __restrict__ Wa2) {
    extern __shared__ float sm[];
    float* AstBuf = sm;
    float* BsBuf  = sm + 2 * GBK * ASTR;

    int tid = threadIdx.x;
    int mbase = blockIdx.y * GBM;
    int nbase = blockIdx.x * GBN;
    int tx = tid & 15, ty = tid >> 4;

    int am = tid & 31, akr = tid >> 5;
    int br = tid >> 4, bc = (tid & 15) * 4;
    const float* Ag = g_meansT + (long long)akr * MTOT + mbase + am * 4;
    const float* Bg = Wa1 + (long long)br * ATTH + nbase + bc;

    u64 acc2[4][4];
    #pragma unroll
    for (int i = 0; i < 4; ++i)
        #pragma unroll
        for (int j = 0; j < 4; ++j) acc2[i][j] = 0ULL;

    float4 pa[4], pb[2];
    #pragma unroll
    for (int p = 0; p < 4; ++p) pa[p] = *(const float4*)(Ag + (long long)(8 * p) * MTOT);
    #pragma unroll
    for (int p = 0; p < 2; ++p) pb[p] = *(const float4*)(Bg + (long long)(16 * p) * ATTH);

    const int NITER = NC / GBK;
    int cur = 0;
    #pragma unroll 1
    for (int it = 0; it < NITER; ++it) {
        float* Ac = AstBuf + cur * GBK * ASTR;
        float* Bc = BsBuf + cur * GBK * GBN;
        #pragma unroll
        for (int p = 0; p < 4; ++p)
            *(float4*)(Ac + (akr + 8 * p) * ASTR + am * 4) = pa[p];
        #pragma unroll
        for (int p = 0; p < 2; ++p)
            *(float4*)(Bc + (br + 16 * p) * GBN + bc) = pb[p];
        __syncthreads();

        if (it + 1 < NITER) {
            long long k0n = (long long)(it + 1) * GBK;
            #pragma unroll
            for (int p = 0; p < 4; ++p)
                pa[p] = *(const float4*)(Ag + (k0n + 8 * p) * MTOT);
            #pragma unroll
            for (int p = 0; p < 2; ++p)
                pb[p] = *(const float4*)(Bg + (k0n + 16 * p) * ATTH);
        }

        #pragma unroll
        for (int kk = 0; kk < GBK; ++kk) {
            const float* Ak = Ac + kk * ASTR + ty * 8;
            ulonglong2 a01 = *(const ulonglong2*)(Ak);
            ulonglong2 a23 = *(const ulonglong2*)(Ak + 4);
            float4 b4 = *(const float4*)(Bc + kk * GBN + tx * 4);
            u64 a2[4] = { a01.x, a01.y, a23.x, a23.y };
            u64 bd[4];
            PACK_DUP_F32X2(bd[0], b4.x);
            PACK_DUP_F32X2(bd[1], b4.y);
            PACK_DUP_F32X2(bd[2], b4.z);
            PACK_DUP_F32X2(bd[3], b4.w);
            #pragma unroll
            for (int mp = 0; mp < 4; ++mp) {
                FMA_F32X2(acc2[mp][0], a2[mp], bd[0], acc2[mp][0]);
                FMA_F32X2(acc2[mp][1], a2[mp], bd[1], acc2[mp][1]);
                FMA_F32X2(acc2[mp][2], a2[mp], bd[2], acc2[mp][2]);
                FMA_F32X2(acc2[mp][3], a2[mp], bd[3], acc2[mp][3]);
            }
        }
        cur ^= 1;
    }

    float b1[4], w2[4];
    #pragma unroll
    for (int j = 0; j < 4; ++j) {
        int n = nbase + tx * 4 + j;
        b1[j] = ba1[n];
        w2[j] = Wa2[n];
    }
    #pragma unroll
    for (int mp = 0; mp < 4; ++mp) {
        float p0 = 0.0f, p1 = 0.0f;
        #pragma unroll
        for (int j = 0; j < 4; ++j) {
            unsigned lo, hi;
            UNPACK_F32X2(lo, hi, acc2[mp][j]);
            float h0 = fmaxf(__uint_as_float(lo) + b1[j], 0.0f);
            float h1 = fmaxf(__uint_as_float(hi) + b1[j], 0.0f);
            p0 += h0 * w2[j];
            p1 += h1 * w2[j];
        }
        #pragma unroll
        for (int o = 8; o > 0; o >>= 1) {
            p0 += __shfl_xor_sync(0xffffffffu, p0, o);
            p1 += __shfl_xor_sync(0xffffffffu, p1, o);
        }
        if (tx == 0) {
            atomicAdd(&g_att[mbase + ty * 8 + 2 * mp + 0], p0);
            atomicAdd(&g_att[mbase + ty * 8 + 2 * mp + 1], p1);
        }
    }
}

// ============================================================
// Kernel 5: fused softmax + weighted mean + partial class dots.
// ============================================================
__global__ void wm_kernel(const float* __restrict__ Wh,
                          const float* __restrict__ ba2,
                          float* __restrict__ out) {
    int b = blockIdx.y, cg = blockIdx.x, t = threadIdx.x;
    int lane = t & 31, w = t >> 5;
    __shared__ float satt[NSG];
    __shared__ float red[4];

    float v = g_att[b * NSG + t] + ba2[0];
    float m = v;
    #pragma unroll
    for (int o = 16; o > 0; o >>= 1) m = fmaxf(m, __shfl_xor_sync(0xffffffffu, m, o));
    if (lane == 0) red[w] = m;
    __syncthreads();
    m = fmaxf(fmaxf(red[0], red[1]), fmaxf(red[2], red[3]));
    float e = expf(v - m);
    float s = e;
    #pragma unroll
    for (int o = 16; o > 0; o >>= 1) s += __shfl_xor_sync(0xffffffffu, s, o);
    __syncthreads();
    if (lane == 0) red[w] = s;
    __syncthreads();
    s = red[0] + red[1] + red[2] + red[3];
    satt[t] = e / s;
    __syncthreads();

    int c = cg * 128 + t;
    float wm = 0.0f;
    const float* mp = g_means + (long long)b * NSG * NC + c;
    #pragma unroll 8
    for (int sg = 0; sg < NSG; ++sg) wm += satt[sg] * mp[(long long)sg * NC];

    const float* whr = Wh + (long long)c * NCLS;
    #pragma unroll 1
    for (int cls = 0; cls < NCLS; ++cls) {
        float p = wm * whr[cls];
        #pragma unroll
        for (int o = 16; o > 0; o >>= 1) p += __shfl_xor_sync(0xffffffffu, p, o);
        if (lane == 0) atomicAdd(&out[b * NCLS + cls], p);
    }
}

// ============================================================
// Kernel 6: BCE-with-logits loss, mean over all 608 elements.
// ============================================================
__global__ void loss_kernel(const float* __restrict__ target,
                            float* __restrict__ out, int out_size) {
    const int n = NB * NCLS;   // 608
    int t = threadIdx.x;
    float v = 0.0f;
    if (t < n) {
        float l = out[t];
        float tg = target[t];
        v = fmaxf(l, 0.0f) - l * tg + log1pf(expf(-fabsf(l)));
    }
    __shared__ float red[32];
    int lane = t & 31, warp = t >> 5;
    #pragma unroll
    for (int o = 16; o > 0; o >>= 1) v += __shfl_xor_sync(0xffffffffu, v, o);
    if (lane == 0) red[warp] = v;
    __syncthreads();
    if (t < 32) {
        float s = (t < 20) ? red[t] : 0.0f;
        #pragma unroll
        for (int o = 16; o > 0; o >>= 1) s += __shfl_xor_sync(0xffffffffu, s, o);
        if (t == 0) out[out_size - 1] = s / (float)n;
    }
}

// ============================================================
extern "C" void kernel_launch(void* const* d_in, const int* in_sizes, int n_in,
                              void* d_out, int out_size) {
    const float* x      = (const float*)d_in[0];
    const int*   mask   = (const int*)d_in[1];
    const float* target = (const float*)d_in[2];
    const float* Wa1    = (const float*)d_in[3];
    const float* ba1    = (const float*)d_in[4];
    const float* Wa2    = (const float*)d_in[5];
    const float* ba2    = (const float*)d_in[6];
    const float* Wh     = (const float*)d_in[7];
    const float* bh     = (const float*)d_in[8];
    float* out = (float*)d_out;

    cudaFuncSetAttribute(seg_kernel,
                         cudaFuncAttributeMaxDynamicSharedMemorySize, SEG_SMEM);
    cudaFuncSetAttribute(att_gemm_kernel,
                         cudaFuncAttributeMaxDynamicSharedMemorySize, GEMM_SMEM);

    zero_kernel<<<17, 256>>>(bh, out);                                   // idx 0
    prep_sort_kernel<<<dim3(NTILE, NB), 128>>>(mask);                    // idx 1
    invc_kernel<<<NB, 160>>>();                                          // idx 2
    seg_kernel<<<dim3(16, NB), 256, SEG_SMEM>>>(x);                      // idx 3 (profiled)
    att_gemm_kernel<<<dim3(ATTH / GBN, MTOT / GBM), 256, GEMM_SMEM>>>(Wa1, ba1, Wa2); // idx 4
    wm_kernel<<<dim3(4, NB), 128>>>(Wh, ba2, out);                       // idx 5
    loss_kernel<<<1, 640>>>(target, out, out_size);                      // idx 6
}